// round 11
// baseline (speedup 1.0000x reference)
#include <cuda_runtime.h>
#include <cuda_bf16.h>
#include <stdint.h>

// R11: occupancy experiment — 16 warps (4/SMSP), TQ=256, TKN=32.
// Hypothesis: mma.sync throughput is warp-inflight-limited; 2 warps/SMSP
// cannot fill the HMMA pipe (R6/R9/R10 all pinned at 336 TF/s).

static constexpr int BATCH = 16;
static constexpr int LSEQ  = 2048;
static constexpr int DHEAD = 128;
static constexpr int TQ    = 256;   // q rows per CTA (16 warps x 16 rows)
static constexpr int TKN   = 32;    // keys per tile
static constexpr int NKT   = LSEQ / TKN;   // 64
static constexpr int THREADS = 512;

static constexpr int PAD   = 136;
static constexpr int QT_BYTES = TQ  * PAD * 2;   // 69632 per Q tile (hi or lo)
static constexpr int KT_BYTES = TKN * PAD * 2;   // 8704
static constexpr int SQH = 0;
static constexpr int SQL = QT_BYTES;
static constexpr int SBUF0 = 2 * QT_BYTES;               // 139264
static constexpr int BUF_STRIDE = 4 * KT_BYTES;          // 34816
static constexpr int OKH = 0, OKL = KT_BYTES, OVH = 2 * KT_BYTES, OVL = 3 * KT_BYTES;
static constexpr int SMEM_BYTES = SBUF0 + 2 * BUF_STRIDE;  // 208896

__device__ __align__(16) __nv_bfloat16 g_qh[(size_t)BATCH * LSEQ * DHEAD];
__device__ __align__(16) __nv_bfloat16 g_ql[(size_t)BATCH * LSEQ * DHEAD];
__device__ __align__(16) __nv_bfloat16 g_kh[(size_t)BATCH * LSEQ * DHEAD];
__device__ __align__(16) __nv_bfloat16 g_kl[(size_t)BATCH * LSEQ * DHEAD];
__device__ __align__(16) __nv_bfloat16 g_vh[(size_t)BATCH * LSEQ * DHEAD];
__device__ __align__(16) __nv_bfloat16 g_vl[(size_t)BATCH * LSEQ * DHEAD];

// ---------------- helpers ----------------
__device__ __forceinline__ uint32_t smem_u32(const void* p) {
    uint32_t a;
    asm("{ .reg .u64 t; cvta.to.shared.u64 t, %1; cvt.u32.u64 %0, t; }" : "=r"(a) : "l"(p));
    return a;
}
__device__ __forceinline__ uint32_t pack2(__nv_bfloat16 a, __nv_bfloat16 b) {
    return (uint32_t)__bfloat16_as_ushort(a) | ((uint32_t)__bfloat16_as_ushort(b) << 16);
}
__device__ __forceinline__ void ldsm_x4(uint32_t* r, uint32_t addr) {
    asm volatile("ldmatrix.sync.aligned.m8n8.x4.shared.b16 {%0,%1,%2,%3}, [%4];"
                 : "=r"(r[0]), "=r"(r[1]), "=r"(r[2]), "=r"(r[3]) : "r"(addr));
}
__device__ __forceinline__ void ldsm_x4_t(uint32_t* r, uint32_t addr) {
    asm volatile("ldmatrix.sync.aligned.m8n8.x4.trans.shared.b16 {%0,%1,%2,%3}, [%4];"
                 : "=r"(r[0]), "=r"(r[1]), "=r"(r[2]), "=r"(r[3]) : "r"(addr));
}
__device__ __forceinline__ void mma16816(float* d, const uint32_t* a, const uint32_t* b) {
    asm volatile("mma.sync.aligned.m16n8k16.row.col.f32.bf16.bf16.f32 "
                 "{%0,%1,%2,%3}, {%4,%5,%6,%7}, {%8,%9}, {%0,%1,%2,%3};"
                 : "+f"(d[0]), "+f"(d[1]), "+f"(d[2]), "+f"(d[3])
                 : "r"(a[0]), "r"(a[1]), "r"(a[2]), "r"(a[3]), "r"(b[0]), "r"(b[1]));
}
__device__ __forceinline__ void cp16(uint32_t dst, const void* src) {
    asm volatile("cp.async.cg.shared.global [%0], [%1], 16;" :: "r"(dst), "l"(src));
}
#define CP_COMMIT() asm volatile("cp.async.commit_group;" ::: "memory")

// 32-row tile: 512 chunks of 16B, 512 threads -> 1 each
__device__ __forceinline__ void stage32(uint32_t dstb, const __nv_bfloat16* __restrict__ g, int tid) {
    int row = tid >> 4, c = tid & 15;
    cp16(dstb + row * (PAD * 2) + c * 16, g + row * DHEAD + c * 8);
}
// 256-row tile: 4096 chunks / 512 threads = 8 each
__device__ __forceinline__ void stage256(uint32_t dstb, const __nv_bfloat16* __restrict__ g, int tid) {
    #pragma unroll
    for (int i = 0; i < 8; ++i) {
        int idx = tid + i * THREADS;
        int row = idx >> 4, c = idx & 15;
        cp16(dstb + row * (PAD * 2) + c * 16, g + row * DHEAD + c * 8);
    }
}

// -------- prep: fp32 -> bf16 hi/lo --------
__device__ __forceinline__ void split4(float4 f, __nv_bfloat16* hi, __nv_bfloat16* lo, size_t i4) {
    __nv_bfloat16 h0 = __float2bfloat16_rn(f.x), h1 = __float2bfloat16_rn(f.y);
    __nv_bfloat16 h2 = __float2bfloat16_rn(f.z), h3 = __float2bfloat16_rn(f.w);
    *reinterpret_cast<uint2*>(hi + 4 * i4) = make_uint2(pack2(h0, h1), pack2(h2, h3));
    *reinterpret_cast<uint2*>(lo + 4 * i4) = make_uint2(
        pack2(__float2bfloat16_rn(f.x - __bfloat162float(h0)), __float2bfloat16_rn(f.y - __bfloat162float(h1))),
        pack2(__float2bfloat16_rn(f.z - __bfloat162float(h2)), __float2bfloat16_rn(f.w - __bfloat162float(h3))));
}
__global__ void prep_split(const float* __restrict__ q, const float* __restrict__ k,
                           const float* __restrict__ v) {
    size_t i = (size_t)blockIdx.x * blockDim.x + threadIdx.x;
    split4(reinterpret_cast<const float4*>(q)[i], g_qh, g_ql, i);
    split4(reinterpret_cast<const float4*>(k)[i], g_kh, g_kl, i);
    split4(reinterpret_cast<const float4*>(v)[i], g_vh, g_vl, i);
}

// -------- fused attention + layernorm --------
__global__ void __launch_bounds__(THREADS, 1)
fmha_ln_hmma(const float* __restrict__ MASK, const float* __restrict__ GAMMA,
             const float* __restrict__ BETA, float* __restrict__ OUT) {
    extern __shared__ char sm[];
    const int tid = threadIdx.x;
    const int w   = tid >> 5;          // 0..15
    const int l   = tid & 31;
    const int b   = blockIdx.y;
    const int q0  = blockIdx.x * TQ;

    const int qr  = l >> 2;
    const int qc2 = (l & 3) * 2;
    const int r1  = 16 * w + qr;

    const uint32_t smb = smem_u32(sm);

    const int lr = l & 7, g = l >> 3;
    const int a_row = 16 * w + lr + ((g & 1) << 3);
    const uint32_t a_off   = (uint32_t)(a_row * PAD + ((g >> 1) << 3)) * 2;
    const uint32_t kb4_off = (uint32_t)((lr + ((g >> 1) << 3)) * PAD + ((g & 1) << 3)) * 2;
    const uint32_t vb4_off = (uint32_t)((lr + ((g & 1) << 3)) * PAD + ((g >> 1) << 3)) * 2;

    const size_t qgbase = ((size_t)(b * LSEQ + q0)) * DHEAD;
    const size_t kvbase = ((size_t)b * LSEQ) * DHEAD;

    stage256(smb + SQH, g_qh + qgbase, tid);
    stage256(smb + SQL, g_ql + qgbase, tid);
    CP_COMMIT();
    {
        const uint32_t d0 = smb + SBUF0;
        stage32(d0 + OKH, g_kh + kvbase, tid);
        stage32(d0 + OKL, g_kl + kvbase, tid);
        stage32(d0 + OVH, g_vh + kvbase, tid);
        stage32(d0 + OVL, g_vl + kvbase, tid);
    }
    CP_COMMIT();

    // ---- persistent Q fragments (loaded once) ----
    uint32_t qH[8][4], qL[8][4];
    asm volatile("cp.async.wait_group 1;" ::: "memory");   // Q staged
    __syncthreads();
    #pragma unroll
    for (int kk = 0; kk < 8; ++kk) {
        ldsm_x4(qH[kk], smb + SQH + a_off + kk * 32);
        ldsm_x4(qL[kk], smb + SQL + a_off + kk * 32);
    }

    float o[16][4];
    #pragma unroll
    for (int n = 0; n < 16; ++n) { o[n][0] = o[n][1] = o[n][2] = o[n][3] = 0.f; }
    float Z1 = 0.f, Z2 = 0.f;

    const float* mrow1 = MASK + (size_t)(q0 + r1) * LSEQ;
    const float* mrow2 = mrow1 + 8 * LSEQ;

    #pragma unroll 1
    for (int kt = 0; kt < NKT; ++kt) {
        if (kt + 1 < NKT) {
            const uint32_t dn = smb + SBUF0 + ((kt + 1) & 1) * BUF_STRIDE;
            const size_t tn = kvbase + (size_t)(kt + 1) * TKN * DHEAD;
            stage32(dn + OKH, g_kh + tn, tid);
            stage32(dn + OKL, g_kl + tn, tid);
            stage32(dn + OVH, g_vh + tn, tid);
            stage32(dn + OVL, g_vl + tn, tid);
            CP_COMMIT();
            asm volatile("cp.async.wait_group 1;" ::: "memory");
        } else {
            asm volatile("cp.async.wait_group 0;" ::: "memory");
        }
        __syncthreads();

        const uint32_t bufb = smb + SBUF0 + (kt & 1) * BUF_STRIDE;
        const uint32_t kh = bufb + OKH, kl = bufb + OKL;
        const uint32_t vh = bufb + OVH, vl = bufb + OVL;

        // ---- S = Qhi*Khi + Qhi*Klo + Qlo*Khi  (32 keys -> c[4][4]) ----
        float c[4][4];
        #pragma unroll
        for (int n = 0; n < 4; ++n) { c[n][0] = c[n][1] = c[n][2] = c[n][3] = 0.f; }

        #pragma unroll
        for (int kk = 0; kk < 8; ++kk) {
            uint32_t bH[2][4], bL[2][4];
            #pragma unroll
            for (int p = 0; p < 2; ++p) {
                const uint32_t toff = (uint32_t)(p * 16 * PAD + kk * 16) * 2;
                ldsm_x4(bH[p], kh + kb4_off + toff);
                ldsm_x4(bL[p], kl + kb4_off + toff);
            }
            #pragma unroll
            for (int p = 0; p < 2; ++p) {
                mma16816(c[2 * p + 0], qH[kk], bH[p] + 0);
                mma16816(c[2 * p + 1], qH[kk], bH[p] + 2);
            }
            #pragma unroll
            for (int p = 0; p < 2; ++p) {
                mma16816(c[2 * p + 0], qH[kk], bL[p] + 0);
                mma16816(c[2 * p + 1], qH[kk], bL[p] + 2);
            }
            #pragma unroll
            for (int p = 0; p < 2; ++p) {
                mma16816(c[2 * p + 0], qL[kk], bH[p] + 0);
                mma16816(c[2 * p + 1], qL[kk], bH[p] + 2);
            }
        }

        // ---- exp/pack both s-groups ----
        uint32_t ph[2][4], pl[2][4];
        #pragma unroll
        for (int s = 0; s < 2; ++s) {
            const float* c0 = c[2 * s + 0];
            const float* c1 = c[2 * s + 1];
            const int cb0 = kt * TKN + 16 * s + qc2;
            const int cb1 = cb0 + 8;
            const float2 mA0 = *reinterpret_cast<const float2*>(mrow1 + cb0);
            const float2 mB0 = *reinterpret_cast<const float2*>(mrow2 + cb0);
            const float2 mA1 = *reinterpret_cast<const float2*>(mrow1 + cb1);
            const float2 mB1 = *reinterpret_cast<const float2*>(mrow2 + cb1);
            float e0 = __expf(c0[0] + mA0.x), e1 = __expf(c0[1] + mA0.y);
            float e2 = __expf(c0[2] + mB0.x), e3 = __expf(c0[3] + mB0.y);
            float f0 = __expf(c1[0] + mA1.x), f1 = __expf(c1[1] + mA1.y);
            float f2 = __expf(c1[2] + mB1.x), f3 = __expf(c1[3] + mB1.y);
            Z1 += (e0 + e1) + (f0 + f1);
            Z2 += (e2 + e3) + (f2 + f3);
            __nv_bfloat16 h0 = __float2bfloat16_rn(e0), h1 = __float2bfloat16_rn(e1);
            __nv_bfloat16 h2 = __float2bfloat16_rn(e2), h3 = __float2bfloat16_rn(e3);
            __nv_bfloat16 g0 = __float2bfloat16_rn(f0), g1 = __float2bfloat16_rn(f1);
            __nv_bfloat16 g2 = __float2bfloat16_rn(f2), g3 = __float2bfloat16_rn(f3);
            ph[s][0] = pack2(h0, h1);
            ph[s][1] = pack2(h2, h3);
            ph[s][2] = pack2(g0, g1);
            ph[s][3] = pack2(g2, g3);
            pl[s][0] = pack2(__float2bfloat16_rn(e0 - __bfloat162float(h0)),
                             __float2bfloat16_rn(e1 - __bfloat162float(h1)));
            pl[s][1] = pack2(__float2bfloat16_rn(e2 - __bfloat162float(h2)),
                             __float2bfloat16_rn(e3 - __bfloat162float(h3)));
            pl[s][2] = pack2(__float2bfloat16_rn(f0 - __bfloat162float(g0)),
                             __float2bfloat16_rn(f1 - __bfloat162float(g1)));
            pl[s][3] = pack2(__float2bfloat16_rn(f2 - __bfloat162float(g2)),
                             __float2bfloat16_rn(f3 - __bfloat162float(g3)));
        }

        // ---- PV: O += Phi*Vhi + Plo*Vhi + Phi*Vlo ----
        #pragma unroll
        for (int s = 0; s < 2; ++s) {
            #pragma unroll
            for (int dp = 0; dp < 8; ++dp) {
                const uint32_t toff = (uint32_t)(s * 16 * PAD + dp * 16) * 2;
                uint32_t vHf[4], vLf[4];
                ldsm_x4_t(vHf, vh + vb4_off + toff);
                ldsm_x4_t(vLf, vl + vb4_off + toff);
                mma16816(o[2 * dp + 0], ph[s], vHf + 0);
                mma16816(o[2 * dp + 1], ph[s], vHf + 2);
                mma16816(o[2 * dp + 0], pl[s], vHf + 0);
                mma16816(o[2 * dp + 1], pl[s], vHf + 2);
                mma16816(o[2 * dp + 0], ph[s], vLf + 0);
                mma16816(o[2 * dp + 1], ph[s], vLf + 2);
            }
        }
        __syncthreads();
    }

    // ---- quad-reduce Z; LayerNorm; write ----
    Z1 += __shfl_xor_sync(0xffffffffu, Z1, 1);
    Z1 += __shfl_xor_sync(0xffffffffu, Z1, 2);
    Z2 += __shfl_xor_sync(0xffffffffu, Z2, 1);
    Z2 += __shfl_xor_sync(0xffffffffu, Z2, 2);
    const float zi1 = 1.0f / Z1, zi2 = 1.0f / Z2;

    float s1a = 0.f, s1b = 0.f, s2a = 0.f, s2b = 0.f;
    #pragma unroll
    for (int n = 0; n < 16; ++n) {
        float x0 = o[n][0] * zi1, x1 = o[n][1] * zi1;
        float x2 = o[n][2] * zi2, x3 = o[n][3] * zi2;
        s1a += x0 + x1;  s1b += x0 * x0 + x1 * x1;
        s2a += x2 + x3;  s2b += x2 * x2 + x3 * x3;
    }
    s1a += __shfl_xor_sync(0xffffffffu, s1a, 1); s1a += __shfl_xor_sync(0xffffffffu, s1a, 2);
    s1b += __shfl_xor_sync(0xffffffffu, s1b, 1); s1b += __shfl_xor_sync(0xffffffffu, s1b, 2);
    s2a += __shfl_xor_sync(0xffffffffu, s2a, 1); s2a += __shfl_xor_sync(0xffffffffu, s2a, 2);
    s2b += __shfl_xor_sync(0xffffffffu, s2b, 1); s2b += __shfl_xor_sync(0xffffffffu, s2b, 2);

    const float mu1 = s1a * (1.0f / 128.0f);
    const float v1  = fmaxf(s1b * (1.0f / 128.0f) - mu1 * mu1, 0.0f);
    const float rs1 = rsqrtf(v1 + 1e-5f);
    const float mu2 = s2a * (1.0f / 128.0f);
    const float v2  = fmaxf(s2b * (1.0f / 128.0f) - mu2 * mu2, 0.0f);
    const float rs2 = rsqrtf(v2 + 1e-5f);

    float* orow1 = OUT + ((size_t)(b * LSEQ + q0 + r1)) * DHEAD;
    float* orow2 = orow1 + 8 * DHEAD;
    #pragma unroll
    for (int n = 0; n < 16; ++n) {
        const int cb = 8 * n + qc2;
        const float2 g2 = *reinterpret_cast<const float2*>(GAMMA + cb);
        const float2 b2 = *reinterpret_cast<const float2*>(BETA + cb);
        float2 y1, y2;
        y1.x = (o[n][0] * zi1 - mu1) * rs1 * g2.x + b2.x;
        y1.y = (o[n][1] * zi1 - mu1) * rs1 * g2.y + b2.y;
        y2.x = (o[n][2] * zi2 - mu2) * rs2 * g2.x + b2.x;
        y2.y = (o[n][3] * zi2 - mu2) * rs2 * g2.y + b2.y;
        *reinterpret_cast<float2*>(orow1 + cb) = y1;
        *reinterpret_cast<float2*>(orow2 + cb) = y2;
    }
}

extern "C" void kernel_launch(void* const* d_in, const int* in_sizes, int n_in,
                              void* d_out, int out_size) {
    (void)in_sizes; (void)n_in; (void)out_size;
    const float* q     = (const float*)d_in[0];
    const float* k     = (const float*)d_in[1];
    const float* v     = (const float*)d_in[2];
    const float* mask  = (const float*)d_in[3];
    const float* gamma = (const float*)d_in[4];
    const float* beta  = (const float*)d_in[5];
    float* out = (float*)d_out;

    cudaFuncSetAttribute(fmha_ln_hmma, cudaFuncAttributeMaxDynamicSharedMemorySize, SMEM_BYTES);

    const int total_f4 = BATCH * LSEQ * DHEAD / 4;
    prep_split<<<total_f4 / 256, 256>>>(q, k, v);
    fmha_ln_hmma<<<dim3(LSEQ / TQ, BATCH), THREADS, SMEM_BYTES>>>(mask, gamma, beta, out);
}

// round 12
// speedup vs baseline: 1.5715x; 1.5715x over previous
#include <cuda_runtime.h>
#include <cuda_bf16.h>
#include <stdint.h>

// R12 = R11 (16 warps, 4/SMSP, TQ=256, TKN=32) with persistent-Q removed:
// Q fragments reloaded from smem per kk so live registers fit the 128-reg cap
// (512 threads). Single-variable fix of R11's spill confound.

static constexpr int BATCH = 16;
static constexpr int LSEQ  = 2048;
static constexpr int DHEAD = 128;
static constexpr int TQ    = 256;   // q rows per CTA (16 warps x 16 rows)
static constexpr int TKN   = 32;    // keys per tile
static constexpr int NKT   = LSEQ / TKN;   // 64
static constexpr int THREADS = 512;

static constexpr int PAD   = 136;
static constexpr int QT_BYTES = TQ  * PAD * 2;   // 69632 per Q tile (hi or lo)
static constexpr int KT_BYTES = TKN * PAD * 2;   // 8704
static constexpr int SQH = 0;
static constexpr int SQL = QT_BYTES;
static constexpr int SBUF0 = 2 * QT_BYTES;               // 139264
static constexpr int BUF_STRIDE = 4 * KT_BYTES;          // 34816
static constexpr int OKH = 0, OKL = KT_BYTES, OVH = 2 * KT_BYTES, OVL = 3 * KT_BYTES;
static constexpr int SMEM_BYTES = SBUF0 + 2 * BUF_STRIDE;  // 208896

__device__ __align__(16) __nv_bfloat16 g_qh[(size_t)BATCH * LSEQ * DHEAD];
__device__ __align__(16) __nv_bfloat16 g_ql[(size_t)BATCH * LSEQ * DHEAD];
__device__ __align__(16) __nv_bfloat16 g_kh[(size_t)BATCH * LSEQ * DHEAD];
__device__ __align__(16) __nv_bfloat16 g_kl[(size_t)BATCH * LSEQ * DHEAD];
__device__ __align__(16) __nv_bfloat16 g_vh[(size_t)BATCH * LSEQ * DHEAD];
__device__ __align__(16) __nv_bfloat16 g_vl[(size_t)BATCH * LSEQ * DHEAD];

// ---------------- helpers ----------------
__device__ __forceinline__ uint32_t smem_u32(const void* p) {
    uint32_t a;
    asm("{ .reg .u64 t; cvta.to.shared.u64 t, %1; cvt.u32.u64 %0, t; }" : "=r"(a) : "l"(p));
    return a;
}
__device__ __forceinline__ uint32_t pack2(__nv_bfloat16 a, __nv_bfloat16 b) {
    return (uint32_t)__bfloat16_as_ushort(a) | ((uint32_t)__bfloat16_as_ushort(b) << 16);
}
__device__ __forceinline__ void ldsm_x4(uint32_t* r, uint32_t addr) {
    asm volatile("ldmatrix.sync.aligned.m8n8.x4.shared.b16 {%0,%1,%2,%3}, [%4];"
                 : "=r"(r[0]), "=r"(r[1]), "=r"(r[2]), "=r"(r[3]) : "r"(addr));
}
__device__ __forceinline__ void ldsm_x4_t(uint32_t* r, uint32_t addr) {
    asm volatile("ldmatrix.sync.aligned.m8n8.x4.trans.shared.b16 {%0,%1,%2,%3}, [%4];"
                 : "=r"(r[0]), "=r"(r[1]), "=r"(r[2]), "=r"(r[3]) : "r"(addr));
}
__device__ __forceinline__ void mma16816(float* d, const uint32_t* a, const uint32_t* b) {
    asm volatile("mma.sync.aligned.m16n8k16.row.col.f32.bf16.bf16.f32 "
                 "{%0,%1,%2,%3}, {%4,%5,%6,%7}, {%8,%9}, {%0,%1,%2,%3};"
                 : "+f"(d[0]), "+f"(d[1]), "+f"(d[2]), "+f"(d[3])
                 : "r"(a[0]), "r"(a[1]), "r"(a[2]), "r"(a[3]), "r"(b[0]), "r"(b[1]));
}
__device__ __forceinline__ void cp16(uint32_t dst, const void* src) {
    asm volatile("cp.async.cg.shared.global [%0], [%1], 16;" :: "r"(dst), "l"(src));
}
#define CP_COMMIT() asm volatile("cp.async.commit_group;" ::: "memory")

// 32-row tile: 512 chunks of 16B, 512 threads -> 1 each
__device__ __forceinline__ void stage32(uint32_t dstb, const __nv_bfloat16* __restrict__ g, int tid) {
    int row = tid >> 4, c = tid & 15;
    cp16(dstb + row * (PAD * 2) + c * 16, g + row * DHEAD + c * 8);
}
// 256-row tile: 4096 chunks / 512 threads = 8 each
__device__ __forceinline__ void stage256(uint32_t dstb, const __nv_bfloat16* __restrict__ g, int tid) {
    #pragma unroll
    for (int i = 0; i < 8; ++i) {
        int idx = tid + i * THREADS;
        int row = idx >> 4, c = idx & 15;
        cp16(dstb + row * (PAD * 2) + c * 16, g + row * DHEAD + c * 8);
    }
}

// -------- prep: fp32 -> bf16 hi/lo --------
__device__ __forceinline__ void split4(float4 f, __nv_bfloat16* hi, __nv_bfloat16* lo, size_t i4) {
    __nv_bfloat16 h0 = __float2bfloat16_rn(f.x), h1 = __float2bfloat16_rn(f.y);
    __nv_bfloat16 h2 = __float2bfloat16_rn(f.z), h3 = __float2bfloat16_rn(f.w);
    *reinterpret_cast<uint2*>(hi + 4 * i4) = make_uint2(pack2(h0, h1), pack2(h2, h3));
    *reinterpret_cast<uint2*>(lo + 4 * i4) = make_uint2(
        pack2(__float2bfloat16_rn(f.x - __bfloat162float(h0)), __float2bfloat16_rn(f.y - __bfloat162float(h1))),
        pack2(__float2bfloat16_rn(f.z - __bfloat162float(h2)), __float2bfloat16_rn(f.w - __bfloat162float(h3))));
}
__global__ void prep_split(const float* __restrict__ q, const float* __restrict__ k,
                           const float* __restrict__ v) {
    size_t i = (size_t)blockIdx.x * blockDim.x + threadIdx.x;
    split4(reinterpret_cast<const float4*>(q)[i], g_qh, g_ql, i);
    split4(reinterpret_cast<const float4*>(k)[i], g_kh, g_kl, i);
    split4(reinterpret_cast<const float4*>(v)[i], g_vh, g_vl, i);
}

// -------- fused attention + layernorm --------
__global__ void __launch_bounds__(THREADS, 1)
fmha_ln_hmma(const float* __restrict__ MASK, const float* __restrict__ GAMMA,
             const float* __restrict__ BETA, float* __restrict__ OUT) {
    extern __shared__ char sm[];
    const int tid = threadIdx.x;
    const int w   = tid >> 5;          // 0..15
    const int l   = tid & 31;
    const int b   = blockIdx.y;
    const int q0  = blockIdx.x * TQ;

    const int qr  = l >> 2;
    const int qc2 = (l & 3) * 2;
    const int r1  = 16 * w + qr;

    const uint32_t smb = smem_u32(sm);

    const int lr = l & 7, g = l >> 3;
    const int a_row = 16 * w + lr + ((g & 1) << 3);
    const uint32_t a_off   = (uint32_t)(a_row * PAD + ((g >> 1) << 3)) * 2;
    const uint32_t kb4_off = (uint32_t)((lr + ((g >> 1) << 3)) * PAD + ((g & 1) << 3)) * 2;
    const uint32_t vb4_off = (uint32_t)((lr + ((g & 1) << 3)) * PAD + ((g >> 1) << 3)) * 2;

    const size_t qgbase = ((size_t)(b * LSEQ + q0)) * DHEAD;
    const size_t kvbase = ((size_t)b * LSEQ) * DHEAD;

    stage256(smb + SQH, g_qh + qgbase, tid);
    stage256(smb + SQL, g_ql + qgbase, tid);
    {
        const uint32_t d0 = smb + SBUF0;
        stage32(d0 + OKH, g_kh + kvbase, tid);
        stage32(d0 + OKL, g_kl + kvbase, tid);
        stage32(d0 + OVH, g_vh + kvbase, tid);
        stage32(d0 + OVL, g_vl + kvbase, tid);
    }
    CP_COMMIT();

    float o[16][4];
    #pragma unroll
    for (int n = 0; n < 16; ++n) { o[n][0] = o[n][1] = o[n][2] = o[n][3] = 0.f; }
    float Z1 = 0.f, Z2 = 0.f;

    const float* mrow1 = MASK + (size_t)(q0 + r1) * LSEQ;
    const float* mrow2 = mrow1 + 8 * LSEQ;

    #pragma unroll 1
    for (int kt = 0; kt < NKT; ++kt) {
        if (kt + 1 < NKT) {
            const uint32_t dn = smb + SBUF0 + ((kt + 1) & 1) * BUF_STRIDE;
            const size_t tn = kvbase + (size_t)(kt + 1) * TKN * DHEAD;
            stage32(dn + OKH, g_kh + tn, tid);
            stage32(dn + OKL, g_kl + tn, tid);
            stage32(dn + OVH, g_vh + tn, tid);
            stage32(dn + OVL, g_vl + tn, tid);
            CP_COMMIT();
            asm volatile("cp.async.wait_group 1;" ::: "memory");
        } else {
            asm volatile("cp.async.wait_group 0;" ::: "memory");
        }
        __syncthreads();

        const uint32_t bufb = smb + SBUF0 + (kt & 1) * BUF_STRIDE;
        const uint32_t kh = bufb + OKH, kl = bufb + OKL;
        const uint32_t vh = bufb + OVH, vl = bufb + OVL;

        // ---- S = Qhi*Khi + Qhi*Klo + Qlo*Khi  (Q frags reloaded per kk) ----
        float c[4][4];
        #pragma unroll
        for (int n = 0; n < 4; ++n) { c[n][0] = c[n][1] = c[n][2] = c[n][3] = 0.f; }

        #pragma unroll
        for (int kk = 0; kk < 8; ++kk) {
            uint32_t qHk[4], qLk[4];
            ldsm_x4(qHk, smb + SQH + a_off + kk * 32);
            ldsm_x4(qLk, smb + SQL + a_off + kk * 32);
            uint32_t bH[2][4], bL[2][4];
            #pragma unroll
            for (int p = 0; p < 2; ++p) {
                const uint32_t toff = (uint32_t)(p * 16 * PAD + kk * 16) * 2;
                ldsm_x4(bH[p], kh + kb4_off + toff);
                ldsm_x4(bL[p], kl + kb4_off + toff);
            }
            #pragma unroll
            for (int p = 0; p < 2; ++p) {
                mma16816(c[2 * p + 0], qHk, bH[p] + 0);
                mma16816(c[2 * p + 1], qHk, bH[p] + 2);
            }
            #pragma unroll
            for (int p = 0; p < 2; ++p) {
                mma16816(c[2 * p + 0], qHk, bL[p] + 0);
                mma16816(c[2 * p + 1], qHk, bL[p] + 2);
            }
            #pragma unroll
            for (int p = 0; p < 2; ++p) {
                mma16816(c[2 * p + 0], qLk, bH[p] + 0);
                mma16816(c[2 * p + 1], qLk, bH[p] + 2);
            }
        }

        // ---- exp/pack both s-groups ----
        uint32_t ph[2][4], pl[2][4];
        #pragma unroll
        for (int s = 0; s < 2; ++s) {
            const float* c0 = c[2 * s + 0];
            const float* c1 = c[2 * s + 1];
            const int cb0 = kt * TKN + 16 * s + qc2;
            const int cb1 = cb0 + 8;
            const float2 mA0 = *reinterpret_cast<const float2*>(mrow1 + cb0);
            const float2 mB0 = *reinterpret_cast<const float2*>(mrow2 + cb0);
            const float2 mA1 = *reinterpret_cast<const float2*>(mrow1 + cb1);
            const float2 mB1 = *reinterpret_cast<const float2*>(mrow2 + cb1);
            float e0 = __expf(c0[0] + mA0.x), e1 = __expf(c0[1] + mA0.y);
            float e2 = __expf(c0[2] + mB0.x), e3 = __expf(c0[3] + mB0.y);
            float f0 = __expf(c1[0] + mA1.x), f1 = __expf(c1[1] + mA1.y);
            float f2 = __expf(c1[2] + mB1.x), f3 = __expf(c1[3] + mB1.y);
            Z1 += (e0 + e1) + (f0 + f1);
            Z2 += (e2 + e3) + (f2 + f3);
            __nv_bfloat16 h0 = __float2bfloat16_rn(e0), h1 = __float2bfloat16_rn(e1);
            __nv_bfloat16 h2 = __float2bfloat16_rn(e2), h3 = __float2bfloat16_rn(e3);
            __nv_bfloat16 g0 = __float2bfloat16_rn(f0), g1 = __float2bfloat16_rn(f1);
            __nv_bfloat16 g2 = __float2bfloat16_rn(f2), g3 = __float2bfloat16_rn(f3);
            ph[s][0] = pack2(h0, h1);
            ph[s][1] = pack2(h2, h3);
            ph[s][2] = pack2(g0, g1);
            ph[s][3] = pack2(g2, g3);
            pl[s][0] = pack2(__float2bfloat16_rn(e0 - __bfloat162float(h0)),
                             __float2bfloat16_rn(e1 - __bfloat162float(h1)));
            pl[s][1] = pack2(__float2bfloat16_rn(e2 - __bfloat162float(h2)),
                             __float2bfloat16_rn(e3 - __bfloat162float(h3)));
            pl[s][2] = pack2(__float2bfloat16_rn(f0 - __bfloat162float(g0)),
                             __float2bfloat16_rn(f1 - __bfloat162float(g1)));
            pl[s][3] = pack2(__float2bfloat16_rn(f2 - __bfloat162float(g2)),
                             __float2bfloat16_rn(f3 - __bfloat162float(g3)));
        }

        // ---- PV: O += Phi*Vhi + Plo*Vhi + Phi*Vlo ----
        #pragma unroll
        for (int s = 0; s < 2; ++s) {
            #pragma unroll
            for (int dp = 0; dp < 8; ++dp) {
                const uint32_t toff = (uint32_t)(s * 16 * PAD + dp * 16) * 2;
                uint32_t vHf[4], vLf[4];
                ldsm_x4_t(vHf, vh + vb4_off + toff);
                ldsm_x4_t(vLf, vl + vb4_off + toff);
                mma16816(o[2 * dp + 0], ph[s], vHf + 0);
                mma16816(o[2 * dp + 1], ph[s], vHf + 2);
                mma16816(o[2 * dp + 0], pl[s], vHf + 0);
                mma16816(o[2 * dp + 1], pl[s], vHf + 2);
                mma16816(o[2 * dp + 0], ph[s], vLf + 0);
                mma16816(o[2 * dp + 1], ph[s], vLf + 2);
            }
        }
        __syncthreads();
    }

    // ---- quad-reduce Z; LayerNorm; write ----
    Z1 += __shfl_xor_sync(0xffffffffu, Z1, 1);
    Z1 += __shfl_xor_sync(0xffffffffu, Z1, 2);
    Z2 += __shfl_xor_sync(0xffffffffu, Z2, 1);
    Z2 += __shfl_xor_sync(0xffffffffu, Z2, 2);
    const float zi1 = 1.0f / Z1, zi2 = 1.0f / Z2;

    float s1a = 0.f, s1b = 0.f, s2a = 0.f, s2b = 0.f;
    #pragma unroll
    for (int n = 0; n < 16; ++n) {
        float x0 = o[n][0] * zi1, x1 = o[n][1] * zi1;
        float x2 = o[n][2] * zi2, x3 = o[n][3] * zi2;
        s1a += x0 + x1;  s1b += x0 * x0 + x1 * x1;
        s2a += x2 + x3;  s2b += x2 * x2 + x3 * x3;
    }
    s1a += __shfl_xor_sync(0xffffffffu, s1a, 1); s1a += __shfl_xor_sync(0xffffffffu, s1a, 2);
    s1b += __shfl_xor_sync(0xffffffffu, s1b, 1); s1b += __shfl_xor_sync(0xffffffffu, s1b, 2);
    s2a += __shfl_xor_sync(0xffffffffu, s2a, 1); s2a += __shfl_xor_sync(0xffffffffu, s2a, 2);
    s2b += __shfl_xor_sync(0xffffffffu, s2b, 1); s2b += __shfl_xor_sync(0xffffffffu, s2b, 2);

    const float mu1 = s1a * (1.0f / 128.0f);
    const float v1  = fmaxf(s1b * (1.0f / 128.0f) - mu1 * mu1, 0.0f);
    const float rs1 = rsqrtf(v1 + 1e-5f);
    const float mu2 = s2a * (1.0f / 128.0f);
    const float v2  = fmaxf(s2b * (1.0f / 128.0f) - mu2 * mu2, 0.0f);
    const float rs2 = rsqrtf(v2 + 1e-5f);

    float* orow1 = OUT + ((size_t)(b * LSEQ + q0 + r1)) * DHEAD;
    float* orow2 = orow1 + 8 * DHEAD;
    #pragma unroll
    for (int n = 0; n < 16; ++n) {
        const int cb = 8 * n + qc2;
        const float2 g2 = *reinterpret_cast<const float2*>(GAMMA + cb);
        const float2 b2 = *reinterpret_cast<const float2*>(BETA + cb);
        float2 y1, y2;
        y1.x = (o[n][0] * zi1 - mu1) * rs1 * g2.x + b2.x;
        y1.y = (o[n][1] * zi1 - mu1) * rs1 * g2.y + b2.y;
        y2.x = (o[n][2] * zi2 - mu2) * rs2 * g2.x + b2.x;
        y2.y = (o[n][3] * zi2 - mu2) * rs2 * g2.y + b2.y;
        *reinterpret_cast<float2*>(orow1 + cb) = y1;
        *reinterpret_cast<float2*>(orow2 + cb) = y2;
    }
}

extern "C" void kernel_launch(void* const* d_in, const int* in_sizes, int n_in,
                              void* d_out, int out_size) {
    (void)in_sizes; (void)n_in; (void)out_size;
    const float* q     = (const float*)d_in[0];
    const float* k     = (const float*)d_in[1];
    const float* v     = (const float*)d_in[2];
    const float* mask  = (const float*)d_in[3];
    const float* gamma = (const float*)d_in[4];
    const float* beta  = (const float*)d_in[5];
    float* out = (float*)d_out;

    cudaFuncSetAttribute(fmha_ln_hmma, cudaFuncAttributeMaxDynamicSharedMemorySize, SMEM_BYTES);

    const int total_f4 = BATCH * LSEQ * DHEAD / 4;
    prep_split<<<total_f4 / 256, 256>>>(q, k, v);
    fmha_ln_hmma<<<dim3(LSEQ / TQ, BATCH), THREADS, SMEM_BYTES>>>(mask, gamma, beta, out);
}

// round 13
// speedup vs baseline: 1.8892x; 1.2022x over previous
#include <cuda_runtime.h>
#include <cuda_fp16.h>
#include <stdint.h>

// R13: MMA-instruction-count reduction (the proven bottleneck: mma.sync rate
// ~13cyc/SMSP pins all schedules at ~336 TF/s).
//  - online max-rescaled softmax: P' = exp(s-M) in (0,1] -> single fp16
//  - PV: 3 passes -> 1 pass (P'_f16 x V_f16, f32 accum)
//  - QK: fp16 hi/lo splits (same 3 passes, ~16x better split precision)

static constexpr int BATCH = 16;
static constexpr int LSEQ  = 2048;
static constexpr int DHEAD = 128;
static constexpr int TQ    = 128;
static constexpr int TKN   = 64;
static constexpr int NKT   = LSEQ / TKN;   // 32

static constexpr int PAD   = 136;
static constexpr int QT_BYTES = TQ  * PAD * 2;   // 34816
static constexpr int KT_BYTES = TKN * PAD * 2;   // 17408
static constexpr int SQH = 0;
static constexpr int SQL = QT_BYTES;
static constexpr int SBUF0 = 2 * QT_BYTES;               // 69632
static constexpr int BUF_STRIDE = 3 * KT_BYTES;          // 52224 (KH, KL, V)
static constexpr int OKH = 0, OKL = KT_BYTES, OV = 2 * KT_BYTES;
static constexpr int SMEM_BYTES = SBUF0 + 2 * BUF_STRIDE;  // 174080

__device__ __align__(16) __half g_qh[(size_t)BATCH * LSEQ * DHEAD];
__device__ __align__(16) __half g_ql[(size_t)BATCH * LSEQ * DHEAD];
__device__ __align__(16) __half g_kh[(size_t)BATCH * LSEQ * DHEAD];
__device__ __align__(16) __half g_kl[(size_t)BATCH * LSEQ * DHEAD];
__device__ __align__(16) __half g_v [(size_t)BATCH * LSEQ * DHEAD];

// ---------------- helpers ----------------
__device__ __forceinline__ uint32_t smem_u32(const void* p) {
    uint32_t a;
    asm("{ .reg .u64 t; cvta.to.shared.u64 t, %1; cvt.u32.u64 %0, t; }" : "=r"(a) : "l"(p));
    return a;
}
__device__ __forceinline__ uint32_t pack2h(__half a, __half b) {
    return (uint32_t)__half_as_ushort(a) | ((uint32_t)__half_as_ushort(b) << 16);
}
__device__ __forceinline__ void ldsm_x4(uint32_t* r, uint32_t addr) {
    asm volatile("ldmatrix.sync.aligned.m8n8.x4.shared.b16 {%0,%1,%2,%3}, [%4];"
                 : "=r"(r[0]), "=r"(r[1]), "=r"(r[2]), "=r"(r[3]) : "r"(addr));
}
__device__ __forceinline__ void ldsm_x4_t(uint32_t* r, uint32_t addr) {
    asm volatile("ldmatrix.sync.aligned.m8n8.x4.trans.shared.b16 {%0,%1,%2,%3}, [%4];"
                 : "=r"(r[0]), "=r"(r[1]), "=r"(r[2]), "=r"(r[3]) : "r"(addr));
}
// D += A * B  (m16n8k16, row.col, fp16 in, f32 accum)
__device__ __forceinline__ void mma16816(float* d, const uint32_t* a, const uint32_t* b) {
    asm volatile("mma.sync.aligned.m16n8k16.row.col.f32.f16.f16.f32 "
                 "{%0,%1,%2,%3}, {%4,%5,%6,%7}, {%8,%9}, {%0,%1,%2,%3};"
                 : "+f"(d[0]), "+f"(d[1]), "+f"(d[2]), "+f"(d[3])
                 : "r"(a[0]), "r"(a[1]), "r"(a[2]), "r"(a[3]), "r"(b[0]), "r"(b[1]));
}
__device__ __forceinline__ void cp16(uint32_t dst, const void* src) {
    asm volatile("cp.async.cg.shared.global [%0], [%1], 16;" :: "r"(dst), "l"(src));
}
#define CP_COMMIT() asm volatile("cp.async.commit_group;" ::: "memory")

__device__ __forceinline__ void stage64(uint32_t dstb, const __half* __restrict__ g, int tid) {
    #pragma unroll
    for (int i = 0; i < 4; ++i) {
        int idx = tid + i * 256;
        int row = idx >> 4, c = idx & 15;
        cp16(dstb + row * (PAD * 2) + c * 16, g + row * DHEAD + c * 8);
    }
}
__device__ __forceinline__ void stage128(uint32_t dstb, const __half* __restrict__ g, int tid) {
    #pragma unroll
    for (int i = 0; i < 8; ++i) {
        int idx = tid + i * 256;
        int row = idx >> 4, c = idx & 15;
        cp16(dstb + row * (PAD * 2) + c * 16, g + row * DHEAD + c * 8);
    }
}

// -------- prep: fp32 -> fp16 hi/lo (Q,K) and fp16 (V) --------
__device__ __forceinline__ void split4h(float4 f, __half* hi, __half* lo, size_t i4) {
    __half h0 = __float2half_rn(f.x), h1 = __float2half_rn(f.y);
    __half h2 = __float2half_rn(f.z), h3 = __float2half_rn(f.w);
    *reinterpret_cast<uint2*>(hi + 4 * i4) = make_uint2(pack2h(h0, h1), pack2h(h2, h3));
    *reinterpret_cast<uint2*>(lo + 4 * i4) = make_uint2(
        pack2h(__float2half_rn(f.x - __half2float(h0)), __float2half_rn(f.y - __half2float(h1))),
        pack2h(__float2half_rn(f.z - __half2float(h2)), __float2half_rn(f.w - __half2float(h3))));
}
__global__ void prep_split(const float* __restrict__ q, const float* __restrict__ k,
                           const float* __restrict__ v) {
    size_t i = (size_t)blockIdx.x * blockDim.x + threadIdx.x;
    split4h(reinterpret_cast<const float4*>(q)[i], g_qh, g_ql, i);
    split4h(reinterpret_cast<const float4*>(k)[i], g_kh, g_kl, i);
    float4 fv = reinterpret_cast<const float4*>(v)[i];
    *reinterpret_cast<uint2*>(g_v + 4 * i) = make_uint2(
        pack2h(__float2half_rn(fv.x), __float2half_rn(fv.y)),
        pack2h(__float2half_rn(fv.z), __float2half_rn(fv.w)));
}

// -------- fused attention + layernorm --------
__global__ void __launch_bounds__(256, 1)
fmha_ln_hmma(const float* __restrict__ MASK, const float* __restrict__ GAMMA,
             const float* __restrict__ BETA, float* __restrict__ OUT) {
    extern __shared__ char sm[];
    const int tid = threadIdx.x;
    const int w   = tid >> 5;
    const int l   = tid & 31;
    const int b   = blockIdx.y;
    const int q0  = blockIdx.x * TQ;

    const int qr  = l >> 2;
    const int qc2 = (l & 3) * 2;
    const int r1  = 16 * w + qr;

    const uint32_t smb = smem_u32(sm);

    const int lr = l & 7, g = l >> 3;
    const int a_row = 16 * w + lr + ((g & 1) << 3);
    const uint32_t a_off   = (uint32_t)(a_row * PAD + ((g >> 1) << 3)) * 2;
    const uint32_t kb4_off = (uint32_t)((lr + ((g >> 1) << 3)) * PAD + ((g & 1) << 3)) * 2;
    const uint32_t vb4_off = (uint32_t)((lr + ((g & 1) << 3)) * PAD + ((g >> 1) << 3)) * 2;

    const size_t qgbase = ((size_t)(b * LSEQ + q0)) * DHEAD;
    const size_t kvbase = ((size_t)b * LSEQ) * DHEAD;

    stage128(smb + SQH, g_qh + qgbase, tid);
    stage128(smb + SQL, g_ql + qgbase, tid);
    {
        const uint32_t d0 = smb + SBUF0;
        stage64(d0 + OKH, g_kh + kvbase, tid);
        stage64(d0 + OKL, g_kl + kvbase, tid);
        stage64(d0 + OV,  g_v  + kvbase, tid);
    }
    CP_COMMIT();

    float o[16][4];
    #pragma unroll
    for (int n = 0; n < 16; ++n) { o[n][0] = o[n][1] = o[n][2] = o[n][3] = 0.f; }
    float Z1 = 0.f, Z2 = 0.f;
    float M1 = -1e30f, M2 = -1e30f;

    const float* mrow1 = MASK + (size_t)(q0 + r1) * LSEQ;
    const float* mrow2 = mrow1 + 8 * LSEQ;

    #pragma unroll 1
    for (int kt = 0; kt < NKT; ++kt) {
        if (kt + 1 < NKT) {
            const uint32_t dn = smb + SBUF0 + ((kt + 1) & 1) * BUF_STRIDE;
            const size_t tn = kvbase + (size_t)(kt + 1) * TKN * DHEAD;
            stage64(dn + OKH, g_kh + tn, tid);
            stage64(dn + OKL, g_kl + tn, tid);
            stage64(dn + OV,  g_v  + tn, tid);
            CP_COMMIT();
            asm volatile("cp.async.wait_group 1;" ::: "memory");
        } else {
            asm volatile("cp.async.wait_group 0;" ::: "memory");
        }
        __syncthreads();

        const uint32_t bufb = smb + SBUF0 + (kt & 1) * BUF_STRIDE;
        const uint32_t kh = bufb + OKH, kl = bufb + OKL;
        const uint32_t vv = bufb + OV;

        // ---- prefetch mask fragments ----
        float2 m1r[8], m2r[8];
        #pragma unroll
        for (int n = 0; n < 8; ++n) {
            const int cb = kt * TKN + 8 * n + qc2;
            m1r[n] = *reinterpret_cast<const float2*>(mrow1 + cb);
            m2r[n] = *reinterpret_cast<const float2*>(mrow2 + cb);
        }

        // ---- S = Qhi*Khi + Qhi*Klo + Qlo*Khi  (fp16 splits, f32 accum) ----
        float c[8][4];
        #pragma unroll
        for (int n = 0; n < 8; ++n) { c[n][0] = c[n][1] = c[n][2] = c[n][3] = 0.f; }

        #pragma unroll
        for (int kk = 0; kk < 8; ++kk) {
            uint32_t aH[4], aL[4];
            ldsm_x4(aH, smb + SQH + a_off + kk * 32);
            ldsm_x4(aL, smb + SQL + a_off + kk * 32);
            uint32_t bH[4][4], bL[4][4];
            #pragma unroll
            for (int p = 0; p < 4; ++p) {
                const uint32_t toff = (uint32_t)(p * 16 * PAD + kk * 16) * 2;
                ldsm_x4(bH[p], kh + kb4_off + toff);
                ldsm_x4(bL[p], kl + kb4_off + toff);
            }
            #pragma unroll
            for (int p = 0; p < 4; ++p) {
                mma16816(c[2 * p + 0], aH, bH[p] + 0);
                mma16816(c[2 * p + 1], aH, bH[p] + 2);
            }
            #pragma unroll
            for (int p = 0; p < 4; ++p) {
                mma16816(c[2 * p + 0], aH, bL[p] + 0);
                mma16816(c[2 * p + 1], aH, bL[p] + 2);
            }
            #pragma unroll
            for (int p = 0; p < 4; ++p) {
                mma16816(c[2 * p + 0], aL, bH[p] + 0);
                mma16816(c[2 * p + 1], aL, bH[p] + 2);
            }
        }

        // ---- fold mask; tile row-max; online rescale of O and Z ----
        float m1t = -1e30f, m2t = -1e30f;
        #pragma unroll
        for (int n = 0; n < 8; ++n) {
            c[n][0] += m1r[n].x;  c[n][1] += m1r[n].y;
            c[n][2] += m2r[n].x;  c[n][3] += m2r[n].y;
            m1t = fmaxf(m1t, fmaxf(c[n][0], c[n][1]));
            m2t = fmaxf(m2t, fmaxf(c[n][2], c[n][3]));
        }
        m1t = fmaxf(m1t, __shfl_xor_sync(0xffffffffu, m1t, 1));
        m1t = fmaxf(m1t, __shfl_xor_sync(0xffffffffu, m1t, 2));
        m2t = fmaxf(m2t, __shfl_xor_sync(0xffffffffu, m2t, 1));
        m2t = fmaxf(m2t, __shfl_xor_sync(0xffffffffu, m2t, 2));
        const float Mn1 = fmaxf(M1, m1t);
        const float Mn2 = fmaxf(M2, m2t);
        const float sc1 = __expf(M1 - Mn1);
        const float sc2 = __expf(M2 - Mn2);
        M1 = Mn1; M2 = Mn2;
        Z1 *= sc1; Z2 *= sc2;
        #pragma unroll
        for (int n = 0; n < 16; ++n) {
            o[n][0] *= sc1; o[n][1] *= sc1;
            o[n][2] *= sc2; o[n][3] *= sc2;
        }

        // ---- per s-group: P' = exp(s - M) in fp16; PV single pass ----
        #pragma unroll
        for (int s = 0; s < 4; ++s) {
            const float* c0 = c[2 * s + 0];
            const float* c1 = c[2 * s + 1];
            float e0 = __expf(c0[0] - M1), e1 = __expf(c0[1] - M1);
            float e2 = __expf(c0[2] - M2), e3 = __expf(c0[3] - M2);
            float f0 = __expf(c1[0] - M1), f1 = __expf(c1[1] - M1);
            float f2 = __expf(c1[2] - M2), f3 = __expf(c1[3] - M2);
            Z1 += (e0 + e1) + (f0 + f1);
            Z2 += (e2 + e3) + (f2 + f3);
            uint32_t ph[4];
            ph[0] = pack2h(__float2half_rn(e0), __float2half_rn(e1));
            ph[1] = pack2h(__float2half_rn(e2), __float2half_rn(e3));
            ph[2] = pack2h(__float2half_rn(f0), __float2half_rn(f1));
            ph[3] = pack2h(__float2half_rn(f2), __float2half_rn(f3));

            #pragma unroll
            for (int dp = 0; dp < 8; ++dp) {
                const uint32_t toff = (uint32_t)(s * 16 * PAD + dp * 16) * 2;
                uint32_t vf[4];
                ldsm_x4_t(vf, vv + vb4_off + toff);
                mma16816(o[2 * dp + 0], ph, vf + 0);
                mma16816(o[2 * dp + 1], ph, vf + 2);
            }
        }
        __syncthreads();
    }

    // ---- quad-reduce Z; LayerNorm; write ----
    Z1 += __shfl_xor_sync(0xffffffffu, Z1, 1);
    Z1 += __shfl_xor_sync(0xffffffffu, Z1, 2);
    Z2 += __shfl_xor_sync(0xffffffffu, Z2, 1);
    Z2 += __shfl_xor_sync(0xffffffffu, Z2, 2);
    const float zi1 = 1.0f / Z1, zi2 = 1.0f / Z2;

    float s1a = 0.f, s1b = 0.f, s2a = 0.f, s2b = 0.f;
    #pragma unroll
    for (int n = 0; n < 16; ++n) {
        float x0 = o[n][0] * zi1, x1 = o[n][1] * zi1;
        float x2 = o[n][2] * zi2, x3 = o[n][3] * zi2;
        s1a += x0 + x1;  s1b += x0 * x0 + x1 * x1;
        s2a += x2 + x3;  s2b += x2 * x2 + x3 * x3;
    }
    s1a += __shfl_xor_sync(0xffffffffu, s1a, 1); s1a += __shfl_xor_sync(0xffffffffu, s1a, 2);
    s1b += __shfl_xor_sync(0xffffffffu, s1b, 1); s1b += __shfl_xor_sync(0xffffffffu, s1b, 2);
    s2a += __shfl_xor_sync(0xffffffffu, s2a, 1); s2a += __shfl_xor_sync(0xffffffffu, s2a, 2);
    s2b += __shfl_xor_sync(0xffffffffu, s2b, 1); s2b += __shfl_xor_sync(0xffffffffu, s2b, 2);

    const float mu1 = s1a * (1.0f / 128.0f);
    const float v1  = fmaxf(s1b * (1.0f / 128.0f) - mu1 * mu1, 0.0f);
    const float rs1 = rsqrtf(v1 + 1e-5f);
    const float mu2 = s2a * (1.0f / 128.0f);
    const float v2  = fmaxf(s2b * (1.0f / 128.0f) - mu2 * mu2, 0.0f);
    const float rs2 = rsqrtf(v2 + 1e-5f);

    float* orow1 = OUT + ((size_t)(b * LSEQ + q0 + r1)) * DHEAD;
    float* orow2 = orow1 + 8 * DHEAD;
    #pragma unroll
    for (int n = 0; n < 16; ++n) {
        const int cb = 8 * n + qc2;
        const float2 g2 = *reinterpret_cast<const float2*>(GAMMA + cb);
        const float2 b2 = *reinterpret_cast<const float2*>(BETA + cb);
        float2 y1, y2;
        y1.x = (o[n][0] * zi1 - mu1) * rs1 * g2.x + b2.x;
        y1.y = (o[n][1] * zi1 - mu1) * rs1 * g2.y + b2.y;
        y2.x = (o[n][2] * zi2 - mu2) * rs2 * g2.x + b2.x;
        y2.y = (o[n][3] * zi2 - mu2) * rs2 * g2.y + b2.y;
        *reinterpret_cast<float2*>(orow1 + cb) = y1;
        *reinterpret_cast<float2*>(orow2 + cb) = y2;
    }
}

extern "C" void kernel_launch(void* const* d_in, const int* in_sizes, int n_in,
                              void* d_out, int out_size) {
    (void)in_sizes; (void)n_in; (void)out_size;
    const float* q     = (const float*)d_in[0];
    const float* k     = (const float*)d_in[1];
    const float* v     = (const float*)d_in[2];
    const float* mask  = (const float*)d_in[3];
    const float* gamma = (const float*)d_in[4];
    const float* beta  = (const float*)d_in[5];
    float* out = (float*)d_out;

    cudaFuncSetAttribute(fmha_ln_hmma, cudaFuncAttributeMaxDynamicSharedMemorySize, SMEM_BYTES);

    const int total_f4 = BATCH * LSEQ * DHEAD / 4;
    prep_split<<<total_f4 / 256, 256>>>(q, k, v);
    fmha_ln_hmma<<<dim3(LSEQ / TQ, BATCH), 256, SMEM_BYTES>>>(mask, gamma, beta, out);
}

// round 14
// speedup vs baseline: 1.9522x; 1.0334x over previous
#include <cuda_runtime.h>
#include <cuda_fp16.h>
#include <stdint.h>

// R14 = R13 + half-tile software pipeline: softmax(h) hides under the tensor
// drain of the next MMA batch. Online softmax per 32-key half. Skip O-rescale
// when the running max didn't change (warp-uniform check).

static constexpr int BATCH = 16;
static constexpr int LSEQ  = 2048;
static constexpr int DHEAD = 128;
static constexpr int TQ    = 128;
static constexpr int TKN   = 64;
static constexpr int NKT   = LSEQ / TKN;   // 32

static constexpr int PAD   = 136;
static constexpr int QT_BYTES = TQ  * PAD * 2;
static constexpr int KT_BYTES = TKN * PAD * 2;
static constexpr int SQH = 0;
static constexpr int SQL = QT_BYTES;
static constexpr int SBUF0 = 2 * QT_BYTES;
static constexpr int BUF_STRIDE = 3 * KT_BYTES;          // KH, KL, V
static constexpr int OKH = 0, OKL = KT_BYTES, OV = 2 * KT_BYTES;
static constexpr int SMEM_BYTES = SBUF0 + 2 * BUF_STRIDE;  // 174080

__device__ __align__(16) __half g_qh[(size_t)BATCH * LSEQ * DHEAD];
__device__ __align__(16) __half g_ql[(size_t)BATCH * LSEQ * DHEAD];
__device__ __align__(16) __half g_kh[(size_t)BATCH * LSEQ * DHEAD];
__device__ __align__(16) __half g_kl[(size_t)BATCH * LSEQ * DHEAD];
__device__ __align__(16) __half g_v [(size_t)BATCH * LSEQ * DHEAD];

// ---------------- helpers ----------------
__device__ __forceinline__ uint32_t smem_u32(const void* p) {
    uint32_t a;
    asm("{ .reg .u64 t; cvta.to.shared.u64 t, %1; cvt.u32.u64 %0, t; }" : "=r"(a) : "l"(p));
    return a;
}
__device__ __forceinline__ uint32_t pack2h(__half a, __half b) {
    return (uint32_t)__half_as_ushort(a) | ((uint32_t)__half_as_ushort(b) << 16);
}
__device__ __forceinline__ void ldsm_x4(uint32_t* r, uint32_t addr) {
    asm volatile("ldmatrix.sync.aligned.m8n8.x4.shared.b16 {%0,%1,%2,%3}, [%4];"
                 : "=r"(r[0]), "=r"(r[1]), "=r"(r[2]), "=r"(r[3]) : "r"(addr));
}
__device__ __forceinline__ void ldsm_x4_t(uint32_t* r, uint32_t addr) {
    asm volatile("ldmatrix.sync.aligned.m8n8.x4.trans.shared.b16 {%0,%1,%2,%3}, [%4];"
                 : "=r"(r[0]), "=r"(r[1]), "=r"(r[2]), "=r"(r[3]) : "r"(addr));
}
__device__ __forceinline__ void mma16816(float* d, const uint32_t* a, const uint32_t* b) {
    asm volatile("mma.sync.aligned.m16n8k16.row.col.f32.f16.f16.f32 "
                 "{%0,%1,%2,%3}, {%4,%5,%6,%7}, {%8,%9}, {%0,%1,%2,%3};"
                 : "+f"(d[0]), "+f"(d[1]), "+f"(d[2]), "+f"(d[3])
                 : "r"(a[0]), "r"(a[1]), "r"(a[2]), "r"(a[3]), "r"(b[0]), "r"(b[1]));
}
__device__ __forceinline__ void cp16(uint32_t dst, const void* src) {
    asm volatile("cp.async.cg.shared.global [%0], [%1], 16;" :: "r"(dst), "l"(src));
}
#define CP_COMMIT() asm volatile("cp.async.commit_group;" ::: "memory")

__device__ __forceinline__ void stage64(uint32_t dstb, const __half* __restrict__ g, int tid) {
    #pragma unroll
    for (int i = 0; i < 4; ++i) {
        int idx = tid + i * 256;
        int row = idx >> 4, c = idx & 15;
        cp16(dstb + row * (PAD * 2) + c * 16, g + row * DHEAD + c * 8);
    }
}
__device__ __forceinline__ void stage128(uint32_t dstb, const __half* __restrict__ g, int tid) {
    #pragma unroll
    for (int i = 0; i < 8; ++i) {
        int idx = tid + i * 256;
        int row = idx >> 4, c = idx & 15;
        cp16(dstb + row * (PAD * 2) + c * 16, g + row * DHEAD + c * 8);
    }
}

// -------- prep: fp32 -> fp16 hi/lo (Q,K) and fp16 (V) --------
__device__ __forceinline__ void split4h(float4 f, __half* hi, __half* lo, size_t i4) {
    __half h0 = __float2half_rn(f.x), h1 = __float2half_rn(f.y);
    __half h2 = __float2half_rn(f.z), h3 = __float2half_rn(f.w);
    *reinterpret_cast<uint2*>(hi + 4 * i4) = make_uint2(pack2h(h0, h1), pack2h(h2, h3));
    *reinterpret_cast<uint2*>(lo + 4 * i4) = make_uint2(
        pack2h(__float2half_rn(f.x - __half2float(h0)), __float2half_rn(f.y - __half2float(h1))),
        pack2h(__float2half_rn(f.z - __half2float(h2)), __float2half_rn(f.w - __half2float(h3))));
}
__global__ void prep_split(const float* __restrict__ q, const float* __restrict__ k,
                           const float* __restrict__ v) {
    size_t i = (size_t)blockIdx.x * blockDim.x + threadIdx.x;
    split4h(reinterpret_cast<const float4*>(q)[i], g_qh, g_ql, i);
    split4h(reinterpret_cast<const float4*>(k)[i], g_kh, g_kl, i);
    float4 fv = reinterpret_cast<const float4*>(v)[i];
    *reinterpret_cast<uint2*>(g_v + 4 * i) = make_uint2(
        pack2h(__float2half_rn(fv.x), __float2half_rn(fv.y)),
        pack2h(__float2half_rn(fv.z), __float2half_rn(fv.w)));
}

// -------- fused attention + layernorm --------
__global__ void __launch_bounds__(256, 1)
fmha_ln_hmma(const float* __restrict__ MASK, const float* __restrict__ GAMMA,
             const float* __restrict__ BETA, float* __restrict__ OUT) {
    extern __shared__ char sm[];
    const int tid = threadIdx.x;
    const int w   = tid >> 5;
    const int l   = tid & 31;
    const int b   = blockIdx.y;
    const int q0  = blockIdx.x * TQ;

    const int qr  = l >> 2;
    const int qc2 = (l & 3) * 2;
    const int r1  = 16 * w + qr;

    const uint32_t smb = smem_u32(sm);

    const int lr = l & 7, g = l >> 3;
    const int a_row = 16 * w + lr + ((g & 1) << 3);
    const uint32_t a_off   = (uint32_t)(a_row * PAD + ((g >> 1) << 3)) * 2;
    const uint32_t kb4_off = (uint32_t)((lr + ((g >> 1) << 3)) * PAD + ((g & 1) << 3)) * 2;
    const uint32_t vb4_off = (uint32_t)((lr + ((g & 1) << 3)) * PAD + ((g >> 1) << 3)) * 2;

    const size_t qgbase = ((size_t)(b * LSEQ + q0)) * DHEAD;
    const size_t kvbase = ((size_t)b * LSEQ) * DHEAD;

    stage128(smb + SQH, g_qh + qgbase, tid);
    stage128(smb + SQL, g_ql + qgbase, tid);
    {
        const uint32_t d0 = smb + SBUF0;
        stage64(d0 + OKH, g_kh + kvbase, tid);
        stage64(d0 + OKL, g_kl + kvbase, tid);
        stage64(d0 + OV,  g_v  + kvbase, tid);
    }
    CP_COMMIT();

    float o[16][4];
    #pragma unroll
    for (int n = 0; n < 16; ++n) { o[n][0] = o[n][1] = o[n][2] = o[n][3] = 0.f; }
    float Z1 = 0.f, Z2 = 0.f;
    float M1 = -1e30f, M2 = -1e30f;

    const float* mrow1 = MASK + (size_t)(q0 + r1) * LSEQ;
    const float* mrow2 = mrow1 + 8 * LSEQ;

    #pragma unroll 1
    for (int kt = 0; kt < NKT; ++kt) {
        if (kt + 1 < NKT) {
            const uint32_t dn = smb + SBUF0 + ((kt + 1) & 1) * BUF_STRIDE;
            const size_t tn = kvbase + (size_t)(kt + 1) * TKN * DHEAD;
            stage64(dn + OKH, g_kh + tn, tid);
            stage64(dn + OKL, g_kl + tn, tid);
            stage64(dn + OV,  g_v  + tn, tid);
            CP_COMMIT();
            asm volatile("cp.async.wait_group 1;" ::: "memory");
        } else {
            asm volatile("cp.async.wait_group 0;" ::: "memory");
        }
        __syncthreads();

        const uint32_t bufb = smb + SBUF0 + (kt & 1) * BUF_STRIDE;
        const uint32_t kh = bufb + OKH, kl = bufb + OKL;
        const uint32_t vv = bufb + OV;

        // ---- prefetch mask fragments (whole tile) ----
        float2 m1r[8], m2r[8];
        #pragma unroll
        for (int n = 0; n < 8; ++n) {
            const int cb = kt * TKN + 8 * n + qc2;
            m1r[n] = *reinterpret_cast<const float2*>(mrow1 + cb);
            m2r[n] = *reinterpret_cast<const float2*>(mrow2 + cb);
        }

        float c[8][4];
        #pragma unroll
        for (int n = 0; n < 8; ++n) { c[n][0] = c[n][1] = c[n][2] = c[n][3] = 0.f; }

        // ================= S half 1 (keys 0..31 -> c[0..3]) =================
        #pragma unroll
        for (int kk = 0; kk < 8; ++kk) {
            uint32_t aH[4], aL[4];
            ldsm_x4(aH, smb + SQH + a_off + kk * 32);
            ldsm_x4(aL, smb + SQL + a_off + kk * 32);
            #pragma unroll
            for (int p = 0; p < 2; ++p) {
                const uint32_t toff = (uint32_t)(p * 16 * PAD + kk * 16) * 2;
                uint32_t bH[4], bL[4];
                ldsm_x4(bH, kh + kb4_off + toff);
                ldsm_x4(bL, kl + kb4_off + toff);
                mma16816(c[2 * p + 0], aH, bH + 0);
                mma16816(c[2 * p + 1], aH, bH + 2);
                mma16816(c[2 * p + 0], aH, bL + 0);
                mma16816(c[2 * p + 1], aH, bL + 2);
                mma16816(c[2 * p + 0], aL, bH + 0);
                mma16816(c[2 * p + 1], aL, bH + 2);
            }
        }
        // ================= S half 2 issued (keys 32..63 -> c[4..7]) =========
        #pragma unroll
        for (int kk = 0; kk < 8; ++kk) {
            uint32_t aH[4], aL[4];
            ldsm_x4(aH, smb + SQH + a_off + kk * 32);
            ldsm_x4(aL, smb + SQL + a_off + kk * 32);
            #pragma unroll
            for (int p = 2; p < 4; ++p) {
                const uint32_t toff = (uint32_t)(p * 16 * PAD + kk * 16) * 2;
                uint32_t bH[4], bL[4];
                ldsm_x4(bH, kh + kb4_off + toff);
                ldsm_x4(bL, kl + kb4_off + toff);
                mma16816(c[2 * p + 0], aH, bH + 0);
                mma16816(c[2 * p + 1], aH, bH + 2);
                mma16816(c[2 * p + 0], aH, bL + 0);
                mma16816(c[2 * p + 1], aH, bL + 2);
                mma16816(c[2 * p + 0], aL, bH + 0);
                mma16816(c[2 * p + 1], aL, bH + 2);
            }
        }

        // ---- two halves: softmax(h) overlaps tensor drain of prior batch ----
        #pragma unroll
        for (int h = 0; h < 2; ++h) {
            const int nb = 4 * h;             // c index base
            // fold mask + half row-max (reads c[nb..nb+3]; stalls only on h's MMAs)
            float m1t = -1e30f, m2t = -1e30f;
            #pragma unroll
            for (int n = 0; n < 4; ++n) {
                c[nb + n][0] += m1r[nb + n].x;  c[nb + n][1] += m1r[nb + n].y;
                c[nb + n][2] += m2r[nb + n].x;  c[nb + n][3] += m2r[nb + n].y;
                m1t = fmaxf(m1t, fmaxf(c[nb + n][0], c[nb + n][1]));
                m2t = fmaxf(m2t, fmaxf(c[nb + n][2], c[nb + n][3]));
            }
            m1t = fmaxf(m1t, __shfl_xor_sync(0xffffffffu, m1t, 1));
            m1t = fmaxf(m1t, __shfl_xor_sync(0xffffffffu, m1t, 2));
            m2t = fmaxf(m2t, __shfl_xor_sync(0xffffffffu, m2t, 1));
            m2t = fmaxf(m2t, __shfl_xor_sync(0xffffffffu, m2t, 2));
            const bool newmax = (m1t > M1) || (m2t > M2);
            if (__any_sync(0xffffffffu, newmax)) {
                const float Mn1 = fmaxf(M1, m1t);
                const float Mn2 = fmaxf(M2, m2t);
                const float sc1 = __expf(M1 - Mn1);
                const float sc2 = __expf(M2 - Mn2);
                M1 = Mn1; M2 = Mn2;
                Z1 *= sc1; Z2 *= sc2;
                #pragma unroll
                for (int n = 0; n < 16; ++n) {
                    o[n][0] *= sc1; o[n][1] *= sc1;
                    o[n][2] *= sc2; o[n][3] *= sc2;
                }
            }
            // P' = exp(s - M) (fp16), Z accumulate
            uint32_t ph[2][4];
            #pragma unroll
            for (int s = 0; s < 2; ++s) {
                const float* c0 = c[nb + 2 * s + 0];
                const float* c1 = c[nb + 2 * s + 1];
                float e0 = __expf(c0[0] - M1), e1 = __expf(c0[1] - M1);
                float e2 = __expf(c0[2] - M2), e3 = __expf(c0[3] - M2);
                float f0 = __expf(c1[0] - M1), f1 = __expf(c1[1] - M1);
                float f2 = __expf(c1[2] - M2), f3 = __expf(c1[3] - M2);
                Z1 += (e0 + e1) + (f0 + f1);
                Z2 += (e2 + e3) + (f2 + f3);
                ph[s][0] = pack2h(__float2half_rn(e0), __float2half_rn(e1));
                ph[s][1] = pack2h(__float2half_rn(e2), __float2half_rn(e3));
                ph[s][2] = pack2h(__float2half_rn(f0), __float2half_rn(f1));
                ph[s][3] = pack2h(__float2half_rn(f2), __float2half_rn(f3));
            }
            // PV for this half (keys 32h .. 32h+31)
            #pragma unroll
            for (int s = 0; s < 2; ++s) {
                const int sg = 2 * h + s;
                #pragma unroll
                for (int dp = 0; dp < 8; ++dp) {
                    const uint32_t toff = (uint32_t)(sg * 16 * PAD + dp * 16) * 2;
                    uint32_t vf[4];
                    ldsm_x4_t(vf, vv + vb4_off + toff);
                    mma16816(o[2 * dp + 0], ph[s], vf + 0);
                    mma16816(o[2 * dp + 1], ph[s], vf + 2);
                }
            }
        }
        __syncthreads();
    }

    // ---- quad-reduce Z; LayerNorm; write ----
    Z1 += __shfl_xor_sync(0xffffffffu, Z1, 1);
    Z1 += __shfl_xor_sync(0xffffffffu, Z1, 2);
    Z2 += __shfl_xor_sync(0xffffffffu, Z2, 1);
    Z2 += __shfl_xor_sync(0xffffffffu, Z2, 2);
    const float zi1 = 1.0f / Z1, zi2 = 1.0f / Z2;

    float s1a = 0.f, s1b = 0.f, s2a = 0.f, s2b = 0.f;
    #pragma unroll
    for (int n = 0; n < 16; ++n) {
        float x0 = o[n][0] * zi1, x1 = o[n][1] * zi1;
        float x2 = o[n][2] * zi2, x3 = o[n][3] * zi2;
        s1a += x0 + x1;  s1b += x0 * x0 + x1 * x1;
        s2a += x2 + x3;  s2b += x2 * x2 + x3 * x3;
    }
    s1a += __shfl_xor_sync(0xffffffffu, s1a, 1); s1a += __shfl_xor_sync(0xffffffffu, s1a, 2);
    s1b += __shfl_xor_sync(0xffffffffu, s1b, 1); s1b += __shfl_xor_sync(0xffffffffu, s1b, 2);
    s2a += __shfl_xor_sync(0xffffffffu, s2a, 1); s2a += __shfl_xor_sync(0xffffffffu, s2a, 2);
    s2b += __shfl_xor_sync(0xffffffffu, s2b, 1); s2b += __shfl_xor_sync(0xffffffffu, s2b, 2);

    const float mu1 = s1a * (1.0f / 128.0f);
    const float v1  = fmaxf(s1b * (1.0f / 128.0f) - mu1 * mu1, 0.0f);
    const float rs1 = rsqrtf(v1 + 1e-5f);
    const float mu2 = s2a * (1.0f / 128.0f);
    const float v2  = fmaxf(s2b * (1.0f / 128.0f) - mu2 * mu2, 0.0f);
    const float rs2 = rsqrtf(v2 + 1e-5f);

    float* orow1 = OUT + ((size_t)(b * LSEQ + q0 + r1)) * DHEAD;
    float* orow2 = orow1 + 8 * DHEAD;
    #pragma unroll
    for (int n = 0; n < 16; ++n) {
        const int cb = 8 * n + qc2;
        const float2 g2 = *reinterpret_cast<const float2*>(GAMMA + cb);
        const float2 b2 = *reinterpret_cast<const float2*>(BETA + cb);
        float2 y1, y2;
        y1.x = (o[n][0] * zi1 - mu1) * rs1 * g2.x + b2.x;
        y1.y = (o[n][1] * zi1 - mu1) * rs1 * g2.y + b2.y;
        y2.x = (o[n][2] * zi2 - mu2) * rs2 * g2.x + b2.x;
        y2.y = (o[n][3] * zi2 - mu2) * rs2 * g2.y + b2.y;
        *reinterpret_cast<float2*>(orow1 + cb) = y1;
        *reinterpret_cast<float2*>(orow2 + cb) = y2;
    }
}

extern "C" void kernel_launch(void* const* d_in, const int* in_sizes, int n_in,
                              void* d_out, int out_size) {
    (void)in_sizes; (void)n_in; (void)out_size;
    const float* q     = (const float*)d_in[0];
    const float* k     = (const float*)d_in[1];
    const float* v     = (const float*)d_in[2];
    const float* mask  = (const float*)d_in[3];
    const float* gamma = (const float*)d_in[4];
    const float* beta  = (const float*)d_in[5];
    float* out = (float*)d_out;

    cudaFuncSetAttribute(fmha_ln_hmma, cudaFuncAttributeMaxDynamicSharedMemorySize, SMEM_BYTES);

    const int total_f4 = BATCH * LSEQ * DHEAD / 4;
    prep_split<<<total_f4 / 256, 256>>>(q, k, v);
    fmha_ln_hmma<<<dim3(LSEQ / TQ, BATCH), 256, SMEM_BYTES>>>(mask, gamma, beta, out);
}